// round 2
// baseline (speedup 1.0000x reference)
#include <cuda_runtime.h>
#include <cstdint>

#define Fdim 16
#define Sdim 512
#define Odim 32
#define Bdim 256
#define NCH  16            // shift chunks
#define SC   32            // shifts per chunk
#define BT   16            // batch rows per btile
#define NBT  16            // Bdim / BT
#define SF   (Sdim * Fdim) // 8192 floats per batch row

// Partial maxima: [chunk][b][f][o] = 8 MB, stays L2-resident within the kernel
__device__ float g_partial[NCH * Bdim * Fdim * Odim];
// Arrival counters per btile (zero-init at load; reducer resets -> replay-safe)
__device__ int g_cnt[NBT];

__global__ __launch_bounds__(512, 2) void fused_kernel(
    const float* __restrict__ x, const float* __restrict__ W,
    const float* __restrict__ bias, float* __restrict__ out) {
    extern __shared__ float ws[];   // W chunk [SC][Fdim][Odim] = 64 KB

    const int tid   = threadIdx.x;
    const int btile = blockIdx.x;   // 0..NBT-1
    const int ch    = blockIdx.y;   // 0..NCH-1

    // ---- stage W chunk (64 KB, contiguous float4) ----
    {
        const float4* wsrc = (const float4*)(W + (size_t)ch * SC * Fdim * Odim);
        #pragma unroll
        for (int it = 0; it < 8; ++it)
            ((float4*)ws)[tid + it * 512] = wsrc[tid + it * 512];
    }
    __syncthreads();

    // thread = (o, f-group of 4, b-group of 4 rows); warp-uniform f0/b0
    const int o  = tid & 31;
    const int f0 = ((tid >> 5) & 3) * 4;
    const int b0 = (tid >> 7) * 4;

    // x row pointers: uniform across warp -> broadcast LDG.128, each read once
    const float4* xr0 = (const float4*)(x + (size_t)(btile * BT + b0 + 0) * SF + ch * SC * Fdim + f0);
    const float4* xr1 = (const float4*)(x + (size_t)(btile * BT + b0 + 1) * SF + ch * SC * Fdim + f0);
    const float4* xr2 = (const float4*)(x + (size_t)(btile * BT + b0 + 2) * SF + ch * SC * Fdim + f0);
    const float4* xr3 = (const float4*)(x + (size_t)(btile * BT + b0 + 3) * SF + ch * SC * Fdim + f0);

    const float NEG = __int_as_float(0xff800000);   // -inf
    float acc[4][4];
    #pragma unroll
    for (int i = 0; i < 4; ++i)
        #pragma unroll
        for (int j = 0; j < 4; ++j) acc[i][j] = NEG;

    #pragma unroll 4
    for (int s = 0; s < SC; ++s) {
        // W: lanes stride-1 over o -> conflict-free scalar LDS
        const float w0 = ws[(s * Fdim + f0 + 0) * Odim + o];
        const float w1 = ws[(s * Fdim + f0 + 1) * Odim + o];
        const float w2 = ws[(s * Fdim + f0 + 2) * Odim + o];
        const float w3 = ws[(s * Fdim + f0 + 3) * Odim + o];

        float4 x0 = xr0[s * 4];
        float4 x1 = xr1[s * 4];
        float4 x2 = xr2[s * 4];
        float4 x3 = xr3[s * 4];

        acc[0][0] = fmaxf(acc[0][0], x0.x * w0); acc[0][1] = fmaxf(acc[0][1], x0.y * w1);
        acc[0][2] = fmaxf(acc[0][2], x0.z * w2); acc[0][3] = fmaxf(acc[0][3], x0.w * w3);
        acc[1][0] = fmaxf(acc[1][0], x1.x * w0); acc[1][1] = fmaxf(acc[1][1], x1.y * w1);
        acc[1][2] = fmaxf(acc[1][2], x1.z * w2); acc[1][3] = fmaxf(acc[1][3], x1.w * w3);
        acc[2][0] = fmaxf(acc[2][0], x2.x * w0); acc[2][1] = fmaxf(acc[2][1], x2.y * w1);
        acc[2][2] = fmaxf(acc[2][2], x2.z * w2); acc[2][3] = fmaxf(acc[2][3], x2.w * w3);
        acc[3][0] = fmaxf(acc[3][0], x3.x * w0); acc[3][1] = fmaxf(acc[3][1], x3.y * w1);
        acc[3][2] = fmaxf(acc[3][2], x3.z * w2); acc[3][3] = fmaxf(acc[3][3], x3.w * w3);
    }

    // ---- store partial maxima (coalesced over o) ----
    #pragma unroll
    for (int i = 0; i < 4; ++i) {
        const int bglob = btile * BT + b0 + i;
        #pragma unroll
        for (int j = 0; j < 4; ++j)
            g_partial[((size_t)(ch * Bdim + bglob) * Fdim + (f0 + j)) * Odim + o] = acc[i][j];
    }

    // ---- arrival protocol: last block of this btile does the reduction ----
    __threadfence();
    __syncthreads();
    __shared__ int s_last;
    if (tid == 0) {
        int old = atomicAdd(&g_cnt[btile], 1);
        s_last = (old == NCH - 1);
        if (old == NCH - 1) g_cnt[btile] = 0;   // self-reset for next replay
    }
    __syncthreads();
    if (!s_last) return;
    __threadfence();   // acquire side

    // ---- tail reduction for this btile's 16 rows ----
    // thread = (b row 0..15, o-quad 0..7, f-group 0..3); lane = o4*4 + fg
    const int b2  = tid >> 5;
    const int o4  = (tid >> 2) & 7;
    const int fg  = tid & 3;
    const int bg2 = btile * BT + b2;

    float4 m[4];
    #pragma unroll
    for (int j = 0; j < 4; ++j) { m[j].x = NEG; m[j].y = NEG; m[j].z = NEG; m[j].w = NEG; }

    #pragma unroll 4
    for (int c = 0; c < NCH; ++c) {
        const float4* p = (const float4*)(g_partial
                          + ((size_t)(c * Bdim + bg2) * Fdim + fg * 4) * Odim) + o4;
        #pragma unroll
        for (int j = 0; j < 4; ++j) {
            float4 v = __ldcg(p + j * (Odim / 4));
            m[j].x = fmaxf(m[j].x, v.x); m[j].y = fmaxf(m[j].y, v.y);
            m[j].z = fmaxf(m[j].z, v.z); m[j].w = fmaxf(m[j].w, v.w);
        }
    }

    // sum over this thread's 4 filters
    float4 s4;
    s4.x = (m[0].x + m[1].x) + (m[2].x + m[3].x);
    s4.y = (m[0].y + m[1].y) + (m[2].y + m[3].y);
    s4.z = (m[0].z + m[1].z) + (m[2].z + m[3].z);
    s4.w = (m[0].w + m[1].w) + (m[2].w + m[3].w);

    // sum over f-groups: lanes differing in bits 0-1 share (b, o4)
    #pragma unroll
    for (int d = 1; d <= 2; d <<= 1) {
        s4.x += __shfl_xor_sync(0xffffffffu, s4.x, d);
        s4.y += __shfl_xor_sync(0xffffffffu, s4.y, d);
        s4.z += __shfl_xor_sync(0xffffffffu, s4.z, d);
        s4.w += __shfl_xor_sync(0xffffffffu, s4.w, d);
    }

    if (fg == 0) {
        const float4 bv = __ldg((const float4*)bias + o4);
        float4 r;
        r.x = fmaxf(s4.x + bv.x, 0.0f);
        r.y = fmaxf(s4.y + bv.y, 0.0f);
        r.z = fmaxf(s4.z + bv.z, 0.0f);
        r.w = fmaxf(s4.w + bv.w, 0.0f);
        *((float4*)(out + (size_t)bg2 * Odim) + o4) = r;
    }
}

extern "C" void kernel_launch(void* const* d_in, const int* in_sizes, int n_in,
                              void* d_out, int out_size) {
    const float* x    = (const float*)d_in[0];   // [256, 8192]
    const float* W    = (const float*)d_in[1];   // [8192, 32]
    const float* bias = (const float*)d_in[2];   // [32]
    float* out        = (float*)d_out;           // [256, 32]

    cudaFuncSetAttribute(fused_kernel, cudaFuncAttributeMaxDynamicSharedMemorySize,
                         64 * 1024);

    dim3 grid(NBT, NCH);
    fused_kernel<<<grid, 512, 64 * 1024>>>(x, W, bias, out);
}

// round 3
// speedup vs baseline: 1.5802x; 1.5802x over previous
#include <cuda_runtime.h>
#include <cstdint>

#define Fdim 16
#define Sdim 512
#define Odim 32
#define Bdim 256
#define NCH  16            // shift chunks
#define SC   32            // shifts per chunk
#define BT   16            // batch rows per btile
#define NBT  16            // Bdim / BT
#define SF   (Sdim * Fdim) // floats per batch row

// Partial maxima scratch, pair-packed: [ch][b][g=8][o=32][p=2] = 8 MB (L2-resident)
__device__ float g_partial[NCH * Bdim * 8 * Odim * 2];

__device__ __forceinline__ float2 mul2(float2 a, float2 b) {
    float2 r;
    asm("mul.rn.f32x2 %0, %1, %2;"
        : "=l"(reinterpret_cast<unsigned long long&>(r))
        : "l"(reinterpret_cast<unsigned long long&>(a)),
          "l"(reinterpret_cast<unsigned long long&>(b)));
    return r;
}

// ---------------------------------------------------------------------------
// Kernel 1: per (btile, chunk): partial[ch][b][f][o] = max_{s in chunk} x*W
// ---------------------------------------------------------------------------
__global__ __launch_bounds__(512, 2) void k1_partial(const float* __restrict__ x,
                                                     const float* __restrict__ W) {
    extern __shared__ float sm[];
    float* xs = sm;            // [BT][SC][Fdim] = 8192 floats (32 KB), natural layout
    float* ws = sm + 8192;     // [SC][8][Odim][2] = 16384 floats (64 KB), pair-packed

    const int tid   = threadIdx.x;
    const int btile = blockIdx.x;
    const int ch    = blockIdx.y;

    // ---- stage x tile (coalesced float4) ----
    #pragma unroll
    for (int it = 0; it < 4; ++it) {
        int idx = tid + it * 512;              // 0..2047 float4s
        int b   = idx >> 7;                    // 128 float4 per row
        int t   = idx & 127;
        float4 v = *(const float4*)(x + (size_t)(btile * BT + b) * SF
                                      + ch * SC * Fdim + t * 4);
        *(float4*)(xs + b * (SC * Fdim) + t * 4) = v;
    }

    // ---- stage W chunk, transposed to [s][g][o][pair] (f = 2g+p) ----
    #pragma unroll
    for (int it = 0; it < 4; ++it) {
        int u  = tid + it * 512;               // 0..2047 units
        int s  = u >> 6;
        int g  = (u >> 3) & 7;
        int oq = u & 7;
        const float* wrow = W + ((size_t)(ch * SC + s) * Fdim + 2 * g) * Odim + 4 * oq;
        float4 a = *(const float4*)(wrow);          // f = 2g
        float4 b = *(const float4*)(wrow + Odim);   // f = 2g+1
        float2* dst = (float2*)(ws) + (s * 8 + g) * Odim + 4 * oq;
        dst[0] = make_float2(a.x, b.x);
        dst[1] = make_float2(a.y, b.y);
        dst[2] = make_float2(a.z, b.z);
        dst[3] = make_float2(a.w, b.w);
    }
    __syncthreads();

    // thread = (o lane, f-group fg -> g pair {2fg, 2fg+1}, b-group of 4 rows)
    const int o  = tid & 31;
    const int fg = (tid >> 5) & 3;
    const int b0 = (tid >> 7) * 4;
    const int g0 = fg * 2;

    const float2* wp = (const float2*)ws + g0 * Odim + o;  // +s*256 per shift
    const float4* xv4 = (const float4*)xs;                  // idx ((b)*SC+s)*4 + fg

    const float NEG = __int_as_float(0xff800000);   // -inf
    float2 acc[4][2];
    #pragma unroll
    for (int i = 0; i < 4; ++i) {
        acc[i][0] = make_float2(NEG, NEG);
        acc[i][1] = make_float2(NEG, NEG);
    }

    #pragma unroll 4
    for (int s = 0; s < SC; ++s) {
        // conflict-free LDS.64: lanes stride-1 over o
        const float2 w01 = wp[s * (8 * Odim)];          // (W[s][2g0][o],   W[s][2g0+1][o])
        const float2 w23 = wp[s * (8 * Odim) + Odim];   // (W[s][2g0+2][o], W[s][2g0+3][o])
        #pragma unroll
        for (int i = 0; i < 4; ++i) {
            // uniform address across warp -> broadcast LDS.128
            const float4 xv = xv4[((b0 + i) * SC + s) * 4 + fg];
            float2 p0 = mul2(make_float2(xv.x, xv.y), w01);
            float2 p1 = mul2(make_float2(xv.z, xv.w), w23);
            acc[i][0].x = fmaxf(acc[i][0].x, p0.x);
            acc[i][0].y = fmaxf(acc[i][0].y, p0.y);
            acc[i][1].x = fmaxf(acc[i][1].x, p1.x);
            acc[i][1].y = fmaxf(acc[i][1].y, p1.y);
        }
    }

    // ---- store partials, pair-packed, coalesced STG.64 over o ----
    #pragma unroll
    for (int i = 0; i < 4; ++i) {
        const int bglob = btile * BT + b0 + i;
        float2* dst = (float2*)g_partial + ((size_t)(ch * Bdim + bglob) * 8 + g0) * Odim + o;
        dst[0]    = acc[i][0];
        dst[Odim] = acc[i][1];
    }
}

// ---------------------------------------------------------------------------
// Kernel 2: out[b,o] = relu( bias[o] + sum_f max_ch partial )
// 256 blocks x 128 threads; thread reads one float4 per chunk (coalesced, MLP=16)
// ---------------------------------------------------------------------------
__global__ __launch_bounds__(128) void k2_reduce(const float* __restrict__ bias,
                                                 float* __restrict__ out) {
    const int b = blockIdx.x;
    const int t = threadIdx.x;

    const float NEG = __int_as_float(0xff800000);
    float4 m = make_float4(NEG, NEG, NEG, NEG);

    const float4* base = (const float4*)g_partial;
    #pragma unroll
    for (int c = 0; c < NCH; ++c) {
        float4 v = __ldcg(base + (size_t)(c * Bdim + b) * 128 + t);
        m.x = fmaxf(m.x, v.x); m.y = fmaxf(m.y, v.y);
        m.z = fmaxf(m.z, v.z); m.w = fmaxf(m.w, v.w);
    }

    // thread's float4 covers (g = t/16, o = 2*(t%16)) : [ (o,p0),(o,p1),(o+1,p0),(o+1,p1) ]
    const int g = t >> 4;
    const int o = (t & 15) * 2;
    __shared__ float red[8][Odim + 1];
    red[g][o]     = m.x + m.y;
    red[g][o + 1] = m.z + m.w;
    __syncthreads();

    if (t < Odim) {
        float sum = bias[t];
        #pragma unroll
        for (int gg = 0; gg < 8; ++gg) sum += red[gg][t];
        out[b * Odim + t] = fmaxf(sum, 0.0f);
    }
}

// ---------------------------------------------------------------------------
extern "C" void kernel_launch(void* const* d_in, const int* in_sizes, int n_in,
                              void* d_out, int out_size) {
    const float* x    = (const float*)d_in[0];   // [256, 8192]
    const float* W    = (const float*)d_in[1];   // [8192, 32]
    const float* bias = (const float*)d_in[2];   // [32]
    float* out        = (float*)d_out;           // [256, 32]

    cudaFuncSetAttribute(k1_partial, cudaFuncAttributeMaxDynamicSharedMemorySize,
                         96 * 1024);

    dim3 g1(NBT, NCH);
    k1_partial<<<g1, 512, 96 * 1024>>>(x, W);
    k2_reduce<<<Bdim, 128>>>(bias, out);
}